// round 1
// baseline (speedup 1.0000x reference)
#include <cuda_runtime.h>
#include <math.h>

#define MAXN 100000
#define MAXM 1600000
#define DIMD 128
#define TOPK 16
#define INV_SQRT_D 0.08838834764831845f

// ---------------- device scratch (no allocations allowed) ----------------
__device__ float g_QK[(size_t)MAXN * 256];   // [N][256]: cols 0..127 = Qv, 128..255 = Ku
__device__ float g_H[(size_t)MAXN * DIMD];   // weighted neighbor sum per dst
__device__ float g_WqkT[128 * 256];          // [k][c]: c<128 -> W_Q[c][k], else W_K[c-128][k]
__device__ float g_WsmT[256 * 128];          // [k][c]: k<128 -> W_self[c][k], else W_msg[c][k-128]
__device__ int   g_deg[MAXN];
__device__ int   g_off[MAXN + 1];
__device__ int   g_cur[MAXN];
__device__ int   g_ssrc[MAXM];
__device__ float g_sdec[MAXM];
__device__ int   g_is64;

__device__ __forceinline__ int get_idx(const void* p, int is64, long long i) {
    return is64 ? (int)((const long long*)p)[i] : ((const int*)p)[i];
}

// ---------------- K0: prep (zero deg, transpose weights, detect idx dtype) ----
__global__ void prep_kernel(const void* eidx,
                            const float* __restrict__ Wself, const float* __restrict__ Wmsg,
                            const float* __restrict__ Wq, const float* __restrict__ Wk,
                            int n) {
    int idx = blockIdx.x * blockDim.x + threadIdx.x;
    if (idx < n) g_deg[idx] = 0;
    if (idx < 128 * 256) {
        int k = idx >> 8, c = idx & 255;
        g_WqkT[idx] = (c < 128) ? Wq[c * DIMD + k] : Wk[(c - 128) * DIMD + k];
    }
    if (idx < 256 * 128) {
        int k = idx >> 7, c = idx & 127;
        g_WsmT[idx] = (k < 128) ? Wself[c * DIMD + k] : Wmsg[c * DIMD + (k - 128)];
    }
    if (blockIdx.x == 0) {
        __shared__ int flag;
        if (threadIdx.x == 0) flag = 0;
        __syncthreads();
        // If data is int64 (values < 2^31), every odd 32-bit word is 0.
        const unsigned int* w = (const unsigned int*)eidx;
        if (threadIdx.x < 256 && w[2 * threadIdx.x + 1] != 0u) atomicOr(&flag, 1);
        __syncthreads();
        if (threadIdx.x == 0) g_is64 = flag ? 0 : 1;
    }
}

// ---------------- K2: histogram of dst ----------------
__global__ void hist_kernel(const void* eidx, int m) {
    int e = blockIdx.x * blockDim.x + threadIdx.x;
    if (e >= m) return;
    int is64 = g_is64;
    int d = get_idx(eidx, is64, (long long)m + e);
    atomicAdd(&g_deg[d], 1);
}

// ---------------- K3: single-block chunked exclusive scan ----------------
__global__ void scan_kernel(int n) {
    __shared__ int tmp[1024];
    __shared__ int carry;
    int tid = threadIdx.x;
    if (tid == 0) carry = 0;
    __syncthreads();
    for (int base = 0; base < n; base += 1024) {
        int i = base + tid;
        int v = (i < n) ? g_deg[i] : 0;
        tmp[tid] = v;
        __syncthreads();
        for (int s = 1; s < 1024; s <<= 1) {
            int t = (tid >= s) ? tmp[tid - s] : 0;
            __syncthreads();
            tmp[tid] += t;
            __syncthreads();
        }
        int excl = tmp[tid] - v + carry;
        if (i < n) { g_off[i] = excl; g_cur[i] = excl; }
        __syncthreads();
        if (tid == 0) carry += tmp[1023];
        __syncthreads();
    }
    if (tid == 0) g_off[n] = carry;
}

// ---------------- K4: scatter edges into dst-sorted segments ----------------
__global__ void scatter_kernel(const void* eidx, const float* __restrict__ edt, int m) {
    int e = blockIdx.x * blockDim.x + threadIdx.x;
    if (e >= m) return;
    int is64 = g_is64;
    int s = get_idx(eidx, is64, e);
    int d = get_idx(eidx, is64, (long long)m + e);
    int pos = atomicAdd(&g_cur[d], 1);
    g_ssrc[pos] = s;
    g_sdec[pos] = expf(-edt[e]);
}

// ---------------- K5: per-dst score + top-16 + softmax + gather-accumulate ----
__global__ void __launch_bounds__(256) attn_kernel(const float* __restrict__ X, int n) {
    int warp = (blockIdx.x * blockDim.x + threadIdx.x) >> 5;
    int lane = threadIdx.x & 31;
    if (warp >= n) return;
    int d = warp;
    int off = g_off[d];
    int deg = g_off[d + 1] - off;
    if (deg == 0) {
        ((float4*)g_H)[(size_t)d * 32 + lane] = make_float4(0.f, 0.f, 0.f, 0.f);
        return;
    }
    const float4* QK4 = (const float4*)g_QK;
    float4 q = QK4[(size_t)d * 64 + lane];   // Qv[d]

    float s0 = -INFINITY, s1 = -INFINITY, s2 = -INFINITY, s3 = -INFINITY;
    int r0 = -1, r1 = -1, r2 = -1, r3 = -1;

    int jmax = deg < 128 ? deg : 128;
    for (int j = 0; j < jmax; j++) {
        int src = g_ssrc[off + j];
        float4 k4 = QK4[(size_t)src * 64 + 32 + lane];  // Ku[src]
        float p = q.x * k4.x + q.y * k4.y + q.z * k4.z + q.w * k4.w;
        #pragma unroll
        for (int o = 16; o; o >>= 1) p += __shfl_xor_sync(0xffffffffu, p, o);
        float sc = p * INV_SQRT_D * g_sdec[off + j];
        if ((j & 31) == lane) {
            int sl = j >> 5;
            if (sl == 0) { s0 = sc; r0 = src; }
            else if (sl == 1) { s1 = sc; r1 = src; }
            else if (sl == 2) { s2 = sc; r2 = src; }
            else             { s3 = sc; r3 = src; }
        }
    }
    // pathological deg>128: keep running top-128 via replace-min (correct for any deg)
    for (int j = 128; j < deg; j++) {
        int src = g_ssrc[off + j];
        float4 k4 = QK4[(size_t)src * 64 + 32 + lane];
        float p = q.x * k4.x + q.y * k4.y + q.z * k4.z + q.w * k4.w;
        #pragma unroll
        for (int o = 16; o; o >>= 1) p += __shfl_xor_sync(0xffffffffu, p, o);
        float sc = p * INV_SQRT_D * g_sdec[off + j];
        float mv = s0; int msl = 0;
        if (s1 < mv) { mv = s1; msl = 1; }
        if (s2 < mv) { mv = s2; msl = 2; }
        if (s3 < mv) { mv = s3; msl = 3; }
        float bv = mv; int bl = lane;
        #pragma unroll
        for (int o = 16; o; o >>= 1) {
            float ov = __shfl_xor_sync(0xffffffffu, bv, o);
            int   ol = __shfl_xor_sync(0xffffffffu, bl, o);
            if (ov < bv || (ov == bv && ol < bl)) { bv = ov; bl = ol; }
        }
        if (sc > bv && lane == bl) {
            if (msl == 0) { s0 = sc; r0 = src; }
            else if (msl == 1) { s1 = sc; r1 = src; }
            else if (msl == 2) { s2 = sc; r2 = src; }
            else              { s3 = sc; r3 = src; }
        }
    }

    int K = deg < TOPK ? deg : TOPK;
    float sel_v; int sel_src;
    if (deg <= TOPK) {
        sel_v = s0; sel_src = r0;  // lane j holds edge j; lanes >= deg hold -inf/-1
    } else {
        sel_v = -INFINITY; sel_src = -1;
        for (int it = 0; it < TOPK; it++) {
            float v = s0; int sl = 0;
            if (s1 > v) { v = s1; sl = 1; }
            if (s2 > v) { v = s2; sl = 2; }
            if (s3 > v) { v = s3; sl = 3; }
            float bv = v; int bl = lane;
            #pragma unroll
            for (int o = 16; o; o >>= 1) {
                float ov = __shfl_xor_sync(0xffffffffu, bv, o);
                int   ol = __shfl_xor_sync(0xffffffffu, bl, o);
                if (ov > bv || (ov == bv && ol < bl)) { bv = ov; bl = ol; }
            }
            int bslot = __shfl_sync(0xffffffffu, sl, bl);
            int csrc = (bslot == 0) ? r0 : (bslot == 1) ? r1 : (bslot == 2) ? r2 : r3;
            int bsrc = __shfl_sync(0xffffffffu, csrc, bl);
            if (lane == bl) {
                if (bslot == 0) s0 = -INFINITY;
                else if (bslot == 1) s1 = -INFINITY;
                else if (bslot == 2) s2 = -INFINITY;
                else                 s3 = -INFINITY;
            }
            if (lane == it) { sel_v = bv; sel_src = bsrc; }
        }
    }

    // masked softmax over selected edges
    float mred = (sel_src >= 0) ? sel_v : -INFINITY;
    #pragma unroll
    for (int o = 16; o; o >>= 1) mred = fmaxf(mred, __shfl_xor_sync(0xffffffffu, mred, o));
    float w = (sel_src >= 0) ? expf(sel_v - mred) : 0.f;
    float wsum = w;
    #pragma unroll
    for (int o = 16; o; o >>= 1) wsum += __shfl_xor_sync(0xffffffffu, wsum, o);
    float alpha = w / wsum;   // wsum >= 1 since max term present

    // H[d] = sum_k alpha_k * X[src_k]
    const float4* X4 = (const float4*)X;
    float4 acc = make_float4(0.f, 0.f, 0.f, 0.f);
    for (int k2 = 0; k2 < K; k2++) {
        float a = __shfl_sync(0xffffffffu, alpha, k2);
        int  sr = __shfl_sync(0xffffffffu, sel_src, k2);
        float4 x = X4[(size_t)sr * 32 + lane];
        acc.x += a * x.x; acc.y += a * x.y; acc.z += a * x.z; acc.w += a * x.w;
    }
    ((float4*)g_H)[(size_t)d * 32 + lane] = acc;
}

// ---------------- K1/K6: tiled fp32 GEMM (128x128 tile, 8x8 per thread) -----
// mode 0: QK = X(N,128) * WqkT(128,256)           -> g_QK, grid.x = 2
// mode 1: out = relu(X*WsmT[0:128] + H*WsmT[128:256]) -> Cext, grid.x = 1
__global__ void __launch_bounds__(256, 2) gemm_kernel(const float* __restrict__ A,
                                                      int mode, float* __restrict__ Cext,
                                                      int n) {
    __shared__ float As[128][36];
    __shared__ float Bs[32][128];

    const float* A2; const float* Bt; float* C;
    int ldB, ldC, ktiles, relu;
    if (mode == 0) { A2 = nullptr; Bt = g_WqkT; C = g_QK; ldB = 256; ldC = 256; ktiles = 4; relu = 0; }
    else           { A2 = g_H;     Bt = g_WsmT; C = Cext; ldB = 128; ldC = 128; ktiles = 8; relu = 1; }

    int tid = threadIdx.x;
    int tx = tid & 15;   // 16 col-groups
    int ty = tid >> 4;   // 16 row-groups
    int colOff = blockIdx.x * 128;
    int rowBase = blockIdx.y * 128;

    float acc[8][8];
    #pragma unroll
    for (int i = 0; i < 8; i++)
        #pragma unroll
        for (int j = 0; j < 8; j++) acc[i][j] = 0.f;

    for (int kt = 0; kt < ktiles; kt++) {
        int kb = kt * 32;                 // B row offset (global k)
        const float* Asrc; int ka;
        if (A2 == nullptr || kt < ktiles / 2) { Asrc = A; ka = (A2 == nullptr) ? kb : kb; }
        else { Asrc = A2; ka = kb - (ktiles / 2) * 32; }

        // load A tile (128 x 32) row-major into As[r][k]
        #pragma unroll
        for (int p = 0; p < 4; p++) {
            int f = tid + p * 256;
            int r = f >> 3;
            int c4 = f & 7;
            int grow = rowBase + r;
            float4 v = make_float4(0.f, 0.f, 0.f, 0.f);
            if (grow < n) v = *(const float4*)&Asrc[(size_t)grow * DIMD + ka + c4 * 4];
            *(float4*)&As[r][c4 * 4] = v;
        }
        // load B tile (32 x 128), Bt is [k][c] row-major
        #pragma unroll
        for (int p = 0; p < 4; p++) {
            int f = tid + p * 256;
            int kk = f >> 5;
            int c4 = f & 31;
            float4 v = *(const float4*)&Bt[(size_t)(kb + kk) * ldB + colOff + c4 * 4];
            *(float4*)&Bs[kk][c4 * 4] = v;
        }
        __syncthreads();

        #pragma unroll
        for (int kk = 0; kk < 32; kk++) {
            float a[8];
            #pragma unroll
            for (int i = 0; i < 8; i++) a[i] = As[ty * 8 + i][kk];
            float4 b0 = *(const float4*)&Bs[kk][tx * 4];
            float4 b1 = *(const float4*)&Bs[kk][64 + tx * 4];
            float b[8] = {b0.x, b0.y, b0.z, b0.w, b1.x, b1.y, b1.z, b1.w};
            #pragma unroll
            for (int i = 0; i < 8; i++)
                #pragma unroll
                for (int j = 0; j < 8; j++)
                    acc[i][j] += a[i] * b[j];
        }
        __syncthreads();
    }

    #pragma unroll
    for (int i = 0; i < 8; i++) {
        int grow = rowBase + ty * 8 + i;
        if (grow < n) {
            float o[8];
            #pragma unroll
            for (int j = 0; j < 8; j++) o[j] = relu ? fmaxf(acc[i][j], 0.f) : acc[i][j];
            float* crow = &C[(size_t)grow * ldC + colOff];
            *(float4*)&crow[tx * 4]      = make_float4(o[0], o[1], o[2], o[3]);
            *(float4*)&crow[64 + tx * 4] = make_float4(o[4], o[5], o[6], o[7]);
        }
    }
}

// ---------------- entry ----------------
extern "C" void kernel_launch(void* const* d_in, const int* in_sizes, int n_in,
                              void* d_out, int out_size) {
    const float* X     = (const float*)d_in[0];
    const void*  eidx  = d_in[1];
    const float* edt   = (const float*)d_in[2];
    const float* Wself = (const float*)d_in[3];
    const float* Wmsg  = (const float*)d_in[4];
    const float* Wq    = (const float*)d_in[5];
    const float* Wk    = (const float*)d_in[6];
    float* out = (float*)d_out;

    int n = in_sizes[0] / DIMD;
    int m = in_sizes[2];

    prep_kernel<<<(n + 255) / 256, 256>>>(eidx, Wself, Wmsg, Wq, Wk, n);
    gemm_kernel<<<dim3(2, (n + 127) / 128), 256>>>(X, 0, nullptr, n);
    hist_kernel<<<(m + 255) / 256, 256>>>(eidx, m);
    scan_kernel<<<1, 1024>>>(n);
    scatter_kernel<<<(m + 255) / 256, 256>>>(eidx, edt, m);
    attn_kernel<<<(n + 7) / 8, 256>>>(X, n);
    gemm_kernel<<<dim3(1, (n + 127) / 128), 256>>>(X, 1, out, n);
}

// round 2
// speedup vs baseline: 1.1861x; 1.1861x over previous
#include <cuda_runtime.h>
#include <math.h>

#define MAXN 100000
#define MAXM 1600000
#define DIMD 128
#define TOPK 16
#define INV_SQRT_D 0.08838834764831845f

// ---------------- device scratch (no allocations allowed) ----------------
__device__ float g_QK[(size_t)MAXN * 256];   // [N][256]: cols 0..127 = Qv, 128..255 = Ku
__device__ float g_H[(size_t)MAXN * DIMD];   // weighted neighbor sum per dst
__device__ float g_WqkT[128 * 256];          // [k][c]: c<128 -> W_Q[c][k], else W_K[c-128][k]
__device__ float g_WsmT[256 * 128];          // [k][c]: k<128 -> W_self[c][k], else W_msg[c][k-128]
__device__ int   g_deg[MAXN];
__device__ int   g_off[MAXN];                // start of each dst's contiguous slab
__device__ int   g_cur[MAXN];
__device__ int   g_ssrc[MAXM];
__device__ float g_sdec[MAXM];
__device__ int   g_is64;
__device__ int   g_total;

__device__ __forceinline__ int get_idx(const void* p, int is64, long long i) {
    return is64 ? (int)((const long long*)p)[i] : ((const int*)p)[i];
}

// ---------------- K0: prep (zero deg, transpose weights, detect idx dtype) ----
__global__ void prep_kernel(const void* eidx,
                            const float* __restrict__ Wself, const float* __restrict__ Wmsg,
                            const float* __restrict__ Wq, const float* __restrict__ Wk,
                            int n) {
    int idx = blockIdx.x * blockDim.x + threadIdx.x;
    if (idx == 0) g_total = 0;
    if (idx < n) g_deg[idx] = 0;
    if (idx < 128 * 256) {
        int k = idx >> 8, c = idx & 255;
        g_WqkT[idx] = (c < 128) ? Wq[c * DIMD + k] : Wk[(c - 128) * DIMD + k];
    }
    if (idx < 256 * 128) {
        int k = idx >> 7, c = idx & 127;
        g_WsmT[idx] = (k < 128) ? Wself[c * DIMD + k] : Wmsg[c * DIMD + (k - 128)];
    }
    if (blockIdx.x == 0) {
        __shared__ int flag;
        if (threadIdx.x == 0) flag = 0;
        __syncthreads();
        // If data is int64 (values < 2^31), every odd 32-bit word is 0.
        const unsigned int* w = (const unsigned int*)eidx;
        if (threadIdx.x < 256 && w[2 * threadIdx.x + 1] != 0u) atomicOr(&flag, 1);
        __syncthreads();
        if (threadIdx.x == 0) g_is64 = flag ? 0 : 1;
    }
}

// ---------------- K2: histogram of dst ----------------
__global__ void hist_kernel(const void* eidx, int m) {
    int e = blockIdx.x * blockDim.x + threadIdx.x;
    if (e >= m) return;
    int is64 = g_is64;
    int d = get_idx(eidx, is64, (long long)m + e);
    atomicAdd(&g_deg[d], 1);
}

// ---------------- K3: slab reservation (replaces prefix scan) ----------------
// Segments need only be contiguous, not sorted by dst: each dst grabs deg[d]
// slots off a global cursor. Fully parallel, ~hist cost.
__global__ void offsets_kernel(int n) {
    int d = blockIdx.x * blockDim.x + threadIdx.x;
    if (d >= n) return;
    int deg = g_deg[d];
    int off = deg ? atomicAdd(&g_total, deg) : 0;
    g_off[d] = off;
    g_cur[d] = off;
}

// ---------------- K4: scatter edges into per-dst slabs ----------------
__global__ void scatter_kernel(const void* eidx, const float* __restrict__ edt, int m) {
    int e = blockIdx.x * blockDim.x + threadIdx.x;
    if (e >= m) return;
    int is64 = g_is64;
    int s = get_idx(eidx, is64, e);
    int d = get_idx(eidx, is64, (long long)m + e);
    int pos = atomicAdd(&g_cur[d], 1);
    g_ssrc[pos] = s;
    g_sdec[pos] = expf(-edt[e]);
}

// ---------------- K5: per-dst score + top-16 + softmax + gather-accumulate ----
__global__ void __launch_bounds__(256) attn_kernel(const float* __restrict__ X, int n) {
    int warp = (blockIdx.x * blockDim.x + threadIdx.x) >> 5;
    int lane = threadIdx.x & 31;
    if (warp >= n) return;
    int d = warp;
    int deg = g_deg[d];
    if (deg == 0) {
        ((float4*)g_H)[(size_t)d * 32 + lane] = make_float4(0.f, 0.f, 0.f, 0.f);
        return;
    }
    int off = g_off[d];
    const float4* QK4 = (const float4*)g_QK;
    float4 q = QK4[(size_t)d * 64 + lane];   // Qv[d]

    float s0 = -INFINITY, s1 = -INFINITY, s2 = -INFINITY, s3 = -INFINITY;
    int r0 = -1, r1 = -1, r2 = -1, r3 = -1;

    int jmax = deg < 128 ? deg : 128;
    for (int j = 0; j < jmax; j++) {
        int src = g_ssrc[off + j];
        float4 k4 = QK4[(size_t)src * 64 + 32 + lane];  // Ku[src]
        float p = q.x * k4.x + q.y * k4.y + q.z * k4.z + q.w * k4.w;
        #pragma unroll
        for (int o = 16; o; o >>= 1) p += __shfl_xor_sync(0xffffffffu, p, o);
        float sc = p * INV_SQRT_D * g_sdec[off + j];
        if ((j & 31) == lane) {
            int sl = j >> 5;
            if (sl == 0) { s0 = sc; r0 = src; }
            else if (sl == 1) { s1 = sc; r1 = src; }
            else if (sl == 2) { s2 = sc; r2 = src; }
            else             { s3 = sc; r3 = src; }
        }
    }
    // pathological deg>128: keep running top-128 via replace-min (correct for any deg)
    for (int j = 128; j < deg; j++) {
        int src = g_ssrc[off + j];
        float4 k4 = QK4[(size_t)src * 64 + 32 + lane];
        float p = q.x * k4.x + q.y * k4.y + q.z * k4.z + q.w * k4.w;
        #pragma unroll
        for (int o = 16; o; o >>= 1) p += __shfl_xor_sync(0xffffffffu, p, o);
        float sc = p * INV_SQRT_D * g_sdec[off + j];
        float mv = s0; int msl = 0;
        if (s1 < mv) { mv = s1; msl = 1; }
        if (s2 < mv) { mv = s2; msl = 2; }
        if (s3 < mv) { mv = s3; msl = 3; }
        float bv = mv; int bl = lane;
        #pragma unroll
        for (int o = 16; o; o >>= 1) {
            float ov = __shfl_xor_sync(0xffffffffu, bv, o);
            int   ol = __shfl_xor_sync(0xffffffffu, bl, o);
            if (ov < bv || (ov == bv && ol < bl)) { bv = ov; bl = ol; }
        }
        if (sc > bv && lane == bl) {
            if (msl == 0) { s0 = sc; r0 = src; }
            else if (msl == 1) { s1 = sc; r1 = src; }
            else if (msl == 2) { s2 = sc; r2 = src; }
            else              { s3 = sc; r3 = src; }
        }
    }

    int K = deg < TOPK ? deg : TOPK;
    float sel_v; int sel_src;
    if (deg <= TOPK) {
        sel_v = s0; sel_src = r0;  // lane j holds edge j; lanes >= deg hold -inf/-1
    } else {
        sel_v = -INFINITY; sel_src = -1;
        for (int it = 0; it < TOPK; it++) {
            float v = s0; int sl = 0;
            if (s1 > v) { v = s1; sl = 1; }
            if (s2 > v) { v = s2; sl = 2; }
            if (s3 > v) { v = s3; sl = 3; }
            float bv = v; int bl = lane;
            #pragma unroll
            for (int o = 16; o; o >>= 1) {
                float ov = __shfl_xor_sync(0xffffffffu, bv, o);
                int   ol = __shfl_xor_sync(0xffffffffu, bl, o);
                if (ov > bv || (ov == bv && ol < bl)) { bv = ov; bl = ol; }
            }
            int bslot = __shfl_sync(0xffffffffu, sl, bl);
            int csrc = (bslot == 0) ? r0 : (bslot == 1) ? r1 : (bslot == 2) ? r2 : r3;
            int bsrc = __shfl_sync(0xffffffffu, csrc, bl);
            if (lane == bl) {
                if (bslot == 0) s0 = -INFINITY;
                else if (bslot == 1) s1 = -INFINITY;
                else if (bslot == 2) s2 = -INFINITY;
                else                 s3 = -INFINITY;
            }
            if (lane == it) { sel_v = bv; sel_src = bsrc; }
        }
    }

    // masked softmax over selected edges
    float mred = (sel_src >= 0) ? sel_v : -INFINITY;
    #pragma unroll
    for (int o = 16; o; o >>= 1) mred = fmaxf(mred, __shfl_xor_sync(0xffffffffu, mred, o));
    float w = (sel_src >= 0) ? expf(sel_v - mred) : 0.f;
    float wsum = w;
    #pragma unroll
    for (int o = 16; o; o >>= 1) wsum += __shfl_xor_sync(0xffffffffu, wsum, o);
    float alpha = w / wsum;   // wsum >= 1 since max term present

    // H[d] = sum_k alpha_k * X[src_k]
    const float4* X4 = (const float4*)X;
    float4 acc = make_float4(0.f, 0.f, 0.f, 0.f);
    for (int k2 = 0; k2 < K; k2++) {
        float a = __shfl_sync(0xffffffffu, alpha, k2);
        int  sr = __shfl_sync(0xffffffffu, sel_src, k2);
        float4 x = X4[(size_t)sr * 32 + lane];
        acc.x += a * x.x; acc.y += a * x.y; acc.z += a * x.z; acc.w += a * x.w;
    }
    ((float4*)g_H)[(size_t)d * 32 + lane] = acc;
}

// ---------------- K1/K6: tiled fp32 GEMM (128x128 tile, 8x8 per thread) -----
// mode 0: QK = X(N,128) * WqkT(128,256)           -> g_QK, grid.x = 2
// mode 1: out = relu(X*WsmT[0:128] + H*WsmT[128:256]) -> Cext, grid.x = 1
__global__ void __launch_bounds__(256, 2) gemm_kernel(const float* __restrict__ A,
                                                      int mode, float* __restrict__ Cext,
                                                      int n) {
    __shared__ float As[128][36];
    __shared__ float Bs[32][128];

    const float* A2; const float* Bt; float* C;
    int ldB, ldC, ktiles, relu;
    if (mode == 0) { A2 = nullptr; Bt = g_WqkT; C = g_QK; ldB = 256; ldC = 256; ktiles = 4; relu = 0; }
    else           { A2 = g_H;     Bt = g_WsmT; C = Cext; ldB = 128; ldC = 128; ktiles = 8; relu = 1; }

    int tid = threadIdx.x;
    int tx = tid & 15;   // 16 col-groups
    int ty = tid >> 4;   // 16 row-groups
    int colOff = blockIdx.x * 128;
    int rowBase = blockIdx.y * 128;

    float acc[8][8];
    #pragma unroll
    for (int i = 0; i < 8; i++)
        #pragma unroll
        for (int j = 0; j < 8; j++) acc[i][j] = 0.f;

    for (int kt = 0; kt < ktiles; kt++) {
        int kb = kt * 32;                 // B row offset (global k)
        const float* Asrc; int ka;
        if (A2 == nullptr || kt < ktiles / 2) { Asrc = A; ka = kb; }
        else { Asrc = A2; ka = kb - (ktiles / 2) * 32; }

        // load A tile (128 x 32) row-major into As[r][k]
        #pragma unroll
        for (int p = 0; p < 4; p++) {
            int f = tid + p * 256;
            int r = f >> 3;
            int c4 = f & 7;
            int grow = rowBase + r;
            float4 v = make_float4(0.f, 0.f, 0.f, 0.f);
            if (grow < n) v = *(const float4*)&Asrc[(size_t)grow * DIMD + ka + c4 * 4];
            *(float4*)&As[r][c4 * 4] = v;
        }
        // load B tile (32 x 128), Bt is [k][c] row-major
        #pragma unroll
        for (int p = 0; p < 4; p++) {
            int f = tid + p * 256;
            int kk = f >> 5;
            int c4 = f & 31;
            float4 v = *(const float4*)&Bt[(size_t)(kb + kk) * ldB + colOff + c4 * 4];
            *(float4*)&Bs[kk][c4 * 4] = v;
        }
        __syncthreads();

        #pragma unroll
        for (int kk = 0; kk < 32; kk++) {
            float a[8];
            #pragma unroll
            for (int i = 0; i < 8; i++) a[i] = As[ty * 8 + i][kk];
            float4 b0 = *(const float4*)&Bs[kk][tx * 4];
            float4 b1 = *(const float4*)&Bs[kk][64 + tx * 4];
            float b[8] = {b0.x, b0.y, b0.z, b0.w, b1.x, b1.y, b1.z, b1.w};
            #pragma unroll
            for (int i = 0; i < 8; i++)
                #pragma unroll
                for (int j = 0; j < 8; j++)
                    acc[i][j] += a[i] * b[j];
        }
        __syncthreads();
    }

    #pragma unroll
    for (int i = 0; i < 8; i++) {
        int grow = rowBase + ty * 8 + i;
        if (grow < n) {
            float o[8];
            #pragma unroll
            for (int j = 0; j < 8; j++) o[j] = relu ? fmaxf(acc[i][j], 0.f) : acc[i][j];
            float* crow = &C[(size_t)grow * ldC + colOff];
            *(float4*)&crow[tx * 4]      = make_float4(o[0], o[1], o[2], o[3]);
            *(float4*)&crow[64 + tx * 4] = make_float4(o[4], o[5], o[6], o[7]);
        }
    }
}

// ---------------- entry ----------------
extern "C" void kernel_launch(void* const* d_in, const int* in_sizes, int n_in,
                              void* d_out, int out_size) {
    const float* X     = (const float*)d_in[0];
    const void*  eidx  = d_in[1];
    const float* edt   = (const float*)d_in[2];
    const float* Wself = (const float*)d_in[3];
    const float* Wmsg  = (const float*)d_in[4];
    const float* Wq    = (const float*)d_in[5];
    const float* Wk    = (const float*)d_in[6];
    float* out = (float*)d_out;

    int n = in_sizes[0] / DIMD;
    int m = in_sizes[2];

    prep_kernel<<<(n + 255) / 256, 256>>>(eidx, Wself, Wmsg, Wq, Wk, n);
    gemm_kernel<<<dim3(2, (n + 127) / 128), 256>>>(X, 0, nullptr, n);
    hist_kernel<<<(m + 255) / 256, 256>>>(eidx, m);
    offsets_kernel<<<(n + 255) / 256, 256>>>(n);
    scatter_kernel<<<(m + 255) / 256, 256>>>(eidx, edt, m);
    attn_kernel<<<(n + 7) / 8, 256>>>(X, n);
    gemm_kernel<<<dim3(1, (n + 127) / 128), 256>>>(X, 1, out, n);
}